// round 4
// baseline (speedup 1.0000x reference)
#include <cuda_runtime.h>

// OrbitalSpectralConv: B=8, C=128, H=W=128; kept modes: 32 kx rows x 17 ky cols.
#define NKY   17
#define NMK   32
#define NMODE 544           // 32*17
#define NSLICE 1024         // B*C

// Scratch (allocation is banned -> device globals). 4.46 MB each.
__device__ float2 g_Xf[NSLICE * NMODE];
__device__ float2 g_Y [NSLICE * NMODE];

// ---------------------------------------------------------------------------
// Kernel 1: forward partial DFT per (b,c) slice.
//   G[h][ky]  = sum_w X[h][w] e^{-2pi i ky w/128},           ky = 0..16
//   Xf[mk][ky]= (1/16384) sum_h G[h][ky] e^{-2pi i kx h/128}, kx = mk<17?mk:mk+96
// ---------------------------------------------------------------------------
__global__ __launch_bounds__(256) void k_fwd(const float* __restrict__ X) {
    __shared__ float  Xs[128][33];      // 32-wide w chunk, pad -> conflict-free
    __shared__ float2 Gs[128][NKY];     // [h][ky]
    __shared__ float2 tb[128];          // (cos,sin)(2*pi*t/128)

    const int tid = threadIdx.x;
    if (tid < 128) {
        float s, c;
        sincospif((float)tid * (2.0f / 128.0f), &s, &c);
        tb[tid] = make_float2(c, s);
    }

    const float* Xp = X + (size_t)blockIdx.x * 16384;

    const int h  = tid & 127;
    const int kb = (tid >> 7) * 8;      // half0: ky 0..8, half1: ky 8..16 (ky=8 dup, benign)

    float gr[9], gi[9];
    int   p[9];
    #pragma unroll
    for (int j = 0; j < 9; j++) { gr[j] = 0.f; gi[j] = 0.f; p[j] = 0; }

    for (int w0 = 0; w0 < 128; w0 += 32) {
        #pragma unroll
        for (int r = 0; r < 16; r++) {
            int idx = tid + r * 256;                 // 4096 elems / 256 threads
            Xs[idx >> 5][idx & 31] = Xp[(idx >> 5) * 128 + w0 + (idx & 31)];
        }
        __syncthreads();
        #pragma unroll 4
        for (int wl = 0; wl < 32; wl++) {
            float x = Xs[h][wl];
            #pragma unroll
            for (int j = 0; j < 9; j++) {
                float2 t = tb[p[j] & 127];           // angle = 2pi*ky*w/128
                gr[j] = fmaf( x, t.x, gr[j]);
                gi[j] = fmaf(-x, t.y, gi[j]);
                p[j] += kb + j;                      // ky_j
            }
        }
        __syncthreads();
    }

    #pragma unroll
    for (int j = 0; j < 9; j++)
        Gs[h][kb + j] = make_float2(gr[j], gi[j]);
    __syncthreads();

    float2* Xfp = g_Xf + (size_t)blockIdx.x * NMODE;
    const float inv = 1.0f / 16384.0f;
    for (int o = tid; o < NMODE; o += 256) {
        int mk = o / NKY;
        int ky = o - mk * NKY;
        int kx = (mk < NKY) ? mk : mk + 96;
        float re = 0.f, im = 0.f;
        int pp = 0;
        #pragma unroll 4
        for (int hh = 0; hh < 128; hh++) {
            float2 g = Gs[hh][ky];
            float2 t = tb[pp & 127];
            // g * (c - i s)
            re = fmaf(g.x, t.x, fmaf( g.y, t.y, re));
            im = fmaf(g.y, t.x, fmaf(-g.x, t.y, im));
            pp += kx;
        }
        Xfp[o] = make_float2(re * inv, im * inv);
    }
}

// ---------------------------------------------------------------------------
// Kernel 2: spectral channel mix with on-the-fly skew-Hermitian weight.
//   Y[b,c,m] = sum_ct [ (re[c,ct,m]-re[ct,c,m]) + i(im[c,ct,m]+im[ct,c,m]) ] * Xf[b,ct,m]
// One block per c (128 blocks), one thread per mode m (544 threads).
// 8 batches accumulated in registers per weight load.
// ---------------------------------------------------------------------------
__global__ __launch_bounds__(544, 1) void k_mix(const float* __restrict__ re,
                                                const float* __restrict__ im) {
    const int m = threadIdx.x;          // 0..543
    const int c = blockIdx.x;           // 0..127

    float yr[8], yi[8];
    #pragma unroll
    for (int b = 0; b < 8; b++) { yr[b] = 0.f; yi[b] = 0.f; }

    const float* reA = re + (size_t)c * 128 * NMODE + m;   // [c][ct][m]
    const float* reB = re + (size_t)c * NMODE + m;         // [ct][c][m]
    const float* imA = im + (size_t)c * 128 * NMODE + m;
    const float* imB = im + (size_t)c * NMODE + m;

    #pragma unroll 2
    for (int ct = 0; ct < 128; ct++) {
        float wre = reA[(size_t)ct * NMODE] - reB[(size_t)ct * 128 * NMODE];
        float wim = imA[(size_t)ct * NMODE] + imB[(size_t)ct * 128 * NMODE];
        #pragma unroll
        for (int b = 0; b < 8; b++) {
            float2 x = g_Xf[(size_t)(b * 128 + ct) * NMODE + m];
            yr[b] = fmaf(wre, x.x, fmaf(-wim, x.y, yr[b]));
            yi[b] = fmaf(wre, x.y, fmaf( wim, x.x, yi[b]));
        }
    }
    #pragma unroll
    for (int b = 0; b < 8; b++)
        g_Y[(size_t)(b * 128 + c) * NMODE + m] = make_float2(yr[b], yi[b]);
}

// ---------------------------------------------------------------------------
// Kernel 3: inverse per (b,c) slice.
//   Z[h][ky] = sum_mk Y[mk][ky] e^{+2pi i kx h/128}          (full complex ifft over kx)
//   out[h][w]= sum_{ky=0..16} a_ky ( Re Z cos(2pi ky w/128) - Im Z sin(...) ),
//              a_0 = 1, a_{1..16} = 2   (c2r: Im(Z[.,0]) ignored)
// ---------------------------------------------------------------------------
__global__ __launch_bounds__(256) void k_inv(float* __restrict__ out) {
    __shared__ float2 Ys[NMODE];
    __shared__ float2 Zs[128][NKY];
    __shared__ float2 tb[128];

    const int tid = threadIdx.x;
    if (tid < 128) {
        float s, c;
        sincospif((float)tid * (2.0f / 128.0f), &s, &c);
        tb[tid] = make_float2(c, s);
    }
    const float2* Yp = g_Y + (size_t)blockIdx.x * NMODE;
    for (int i = tid; i < NMODE; i += 256) Ys[i] = Yp[i];
    __syncthreads();

    // ---- Phase A: kx -> h synthesis ----
    {
        const int h  = tid & 127;
        const int kb = (tid >> 7) * 8;   // ky 0..8 / 8..16 (dup at 8, benign)
        float zr[9], zi[9];
        #pragma unroll
        for (int j = 0; j < 9; j++) { zr[j] = 0.f; zi[j] = 0.f; }

        int p = 0;                       // kx = mk for mk 0..16
        for (int mk = 0; mk < NKY; mk++) {
            float2 t = tb[p & 127];
            #pragma unroll
            for (int j = 0; j < 9; j++) {
                float2 y = Ys[mk * NKY + kb + j];
                // y * (c + i s)
                zr[j] = fmaf(y.x, t.x, fmaf(-y.y, t.y, zr[j]));
                zi[j] = fmaf(y.x, t.y, fmaf( y.y, t.x, zi[j]));
            }
            p += h;
        }
        int p2 = 113 * h;                // kx = mk + 96 for mk 17..31 (113..127)
        for (int mk = NKY; mk < NMK; mk++) {
            float2 t = tb[p2 & 127];
            #pragma unroll
            for (int j = 0; j < 9; j++) {
                float2 y = Ys[mk * NKY + kb + j];
                zr[j] = fmaf(y.x, t.x, fmaf(-y.y, t.y, zr[j]));
                zi[j] = fmaf(y.x, t.y, fmaf( y.y, t.x, zi[j]));
            }
            p2 += h;
        }
        #pragma unroll
        for (int j = 0; j < 9; j++)
            Zs[h][kb + j] = make_float2(zr[j], zi[j]);
    }
    __syncthreads();

    // ---- Phase B: ky -> w synthesis (c2r), coalesced stores ----
    {
        const int w  = tid & 127;
        const int h0 = (tid >> 7) * 64;
        float ck[NKY], sk[NKY];
        #pragma unroll
        for (int ky = 0; ky < NKY; ky++) {
            float2 t = tb[(ky * w) & 127];
            float a = ky ? 2.0f : 1.0f;
            ck[ky] =  a * t.x;
            sk[ky] = -a * t.y;
        }
        float* op = out + (size_t)blockIdx.x * 16384 + w;
        for (int h = h0; h < h0 + 64; h++) {
            float acc = 0.f;
            #pragma unroll
            for (int ky = 0; ky < NKY; ky++) {
                float2 z = Zs[h][ky];
                acc = fmaf(z.x, ck[ky], fmaf(z.y, sk[ky], acc));
            }
            op[h * 128] = acc;
        }
    }
}

extern "C" void kernel_launch(void* const* d_in, const int* in_sizes, int n_in,
                              void* d_out, int out_size) {
    const float* X  = (const float*)d_in[0];
    const float* re = (const float*)d_in[1];
    const float* im = (const float*)d_in[2];
    float* out = (float*)d_out;

    k_fwd<<<NSLICE, 256>>>(X);
    k_mix<<<128, 544>>>(re, im);
    k_inv<<<NSLICE, 256>>>(out);
}